// round 17
// baseline (speedup 1.0000x reference)
#include <cuda_runtime.h>
#include <cuda_fp16.h>
#include <cuda_fp8.h>
#include <math.h>
#include <stdint.h>

#define N_TOTAL 8192
#define HALF_N  4096
#define BM      128
#define BN      128
#define MTILES  64               // N_TOTAL / BM
#define NCTAS   304              // 2 per SM, all co-resident
#define PITCHB  144              // 128B fp8 row + 16B pad

#define SMEM_A    0
#define SMEM_B0   18432
#define SMEM_B1   36864
#define SMEM_NI   55296
#define SMEM_NJ0  55808
#define SMEM_NJ1  56320
#define SMEM_TOTAL 56832

__device__ __align__(16) uint8_t g_Y[N_TOTAL * 128];   // 1 MB e4m3 copy
__device__ float g_norm[N_TOTAL];
__device__ float g_rowsum[N_TOTAL];
__device__ float g_diag[HALF_N];
__device__ int   g_done = 0;

// ---------------------------------------------------------------- helpers
__device__ __forceinline__ uint32_t smem_u32(const void* p) {
    uint32_t a;
    asm("{ .reg .u64 t; cvta.to.shared.u64 t, %1; cvt.u32.u64 %0, t; }"
        : "=r"(a) : "l"(p));
    return a;
}
__device__ __forceinline__ void cp_async16(uint32_t dst, const void* src) {
    asm volatile("cp.async.cg.shared.global [%0], [%1], 16;"
                 :: "r"(dst), "l"(src) : "memory");
}
__device__ __forceinline__ void cp_commit() {
    asm volatile("cp.async.commit_group;" ::: "memory");
}
template <int N>
__device__ __forceinline__ void cp_wait() {
    asm volatile("cp.async.wait_group %0;" :: "n"(N) : "memory");
}
__device__ __forceinline__ void mma_fp8(float* c, const uint32_t* a, const uint32_t* b) {
    asm volatile(
        "mma.sync.aligned.m16n8k32.row.col.f32.e4m3.e4m3.f32 "
        "{%0,%1,%2,%3}, {%4,%5,%6,%7}, {%8,%9}, {%0,%1,%2,%3};"
        : "+f"(c[0]), "+f"(c[1]), "+f"(c[2]), "+f"(c[3])
        : "r"(a[0]), "r"(a[1]), "r"(a[2]), "r"(a[3]), "r"(b[0]), "r"(b[1]));
}
__device__ __forceinline__ void ldsm_x4(uint32_t* r, uint32_t addr) {
    asm volatile("ldmatrix.sync.aligned.m8n8.x4.shared.b16 {%0,%1,%2,%3}, [%4];"
                 : "=r"(r[0]), "=r"(r[1]), "=r"(r[2]), "=r"(r[3])
                 : "r"(addr));
}

// ---------------------------------------------------------------------------
// Kernel: fused prep (strided pairs) + spin grid barrier + persistent
// triangular fp8 GEMM (R15 mainloop) with hoisted cp.async addressing.
// ---------------------------------------------------------------------------
__global__ void __launch_bounds__(256, 2)
simsum_kernel(const float* __restrict__ X) {
    extern __shared__ char smem[];
    const uint32_t sb = smem_u32(smem);
    float* nIs = (float*)(smem + SMEM_NI);

    const int tid = threadIdx.x;
    const int wid = tid >> 5, lid = tid & 31;
    const int wm = wid >> 2, wn = wid & 3;     // warp grid 2x4
    const int g = lid >> 2, t = lid & 3;

    // ======================= inline prep =======================
    {
        const float4* X4 = (const float4*)X;
        #pragma unroll 1
        for (int p = blockIdx.x * 8 + wid; p < HALF_N; p += NCTAS * 8) {
            float4 v = X4[(size_t)p * 32 + lid];
            float4 u = X4[(size_t)(p + HALF_N) * 32 + lid];

            float s1 = v.x * v.x + v.y * v.y + v.z * v.z + v.w * v.w;
            float s2 = u.x * u.x + u.y * u.y + u.z * u.z + u.w * u.w;
            float dx = v.x - u.x, dy = v.y - u.y, dz = v.z - u.z, dw = v.w - u.w;
            float sq = dx * dx + dy * dy + dz * dz + dw * dw;
            #pragma unroll
            for (int off = 16; off; off >>= 1) {
                s1 += __shfl_xor_sync(0xffffffffu, s1, off);
                s2 += __shfl_xor_sync(0xffffffffu, s2, off);
                sq += __shfl_xor_sync(0xffffffffu, sq, off);
            }
            if (lid == 0) {
                g_norm[p] = s1;
                g_norm[p + HALF_N] = s2;
                g_rowsum[p] = 0.0f;
                g_rowsum[p + HALF_N] = 0.0f;
                g_diag[p] = 1.0f / (fmaxf(sq, 0.0f) + 1.0f);
            }
            uint32_t a0 = __nv_cvt_float_to_fp8(v.x, __NV_SATFINITE, __NV_E4M3);
            uint32_t a1 = __nv_cvt_float_to_fp8(v.y, __NV_SATFINITE, __NV_E4M3);
            uint32_t a2 = __nv_cvt_float_to_fp8(v.z, __NV_SATFINITE, __NV_E4M3);
            uint32_t a3 = __nv_cvt_float_to_fp8(v.w, __NV_SATFINITE, __NV_E4M3);
            ((uint32_t*)(g_Y + (size_t)p * 128))[lid] =
                a0 | (a1 << 8) | (a2 << 16) | (a3 << 24);
            uint32_t b0 = __nv_cvt_float_to_fp8(u.x, __NV_SATFINITE, __NV_E4M3);
            uint32_t b1 = __nv_cvt_float_to_fp8(u.y, __NV_SATFINITE, __NV_E4M3);
            uint32_t b2 = __nv_cvt_float_to_fp8(u.z, __NV_SATFINITE, __NV_E4M3);
            uint32_t b3 = __nv_cvt_float_to_fp8(u.w, __NV_SATFINITE, __NV_E4M3);
            ((uint32_t*)(g_Y + (size_t)(p + HALF_N) * 128))[lid] =
                b0 | (b1 << 8) | (b2 << 16) | (b3 << 24);
        }
        __threadfence();
        __syncthreads();
        if (tid == 0) {
            atomicAdd(&g_done, 1);
            while (*(volatile int*)&g_done < NCTAS) { }
        }
        __syncthreads();
    }
    // ===========================================================

    const int c = blockIdx.x;
    const int start = 6 * c + min(c, 256);     // 2080 = 256*7 + 48*6
    const int cnt = 6 + (c < 256 ? 1 : 0);

    int cbi = 0;
    #pragma unroll 1
    while ((cbi + 1) * (129 - (cbi + 1)) / 2 <= start) ++cbi;
    int cbj = cbi + (start - cbi * (129 - cbi) / 2);

    const uint32_t arel = (uint32_t)((wm * 64 + (lid & 15)) * PITCHB + (lid >> 4) * 16);
    const uint32_t brel = (uint32_t)((wn * 32 + (lid >> 4) * 8 + (lid & 7)) * PITCHB
                                     + ((lid >> 3) & 1) * 16);

    // hoisted per-thread cp.async offsets
    uint32_t dOff[4], sOff[4];
    #pragma unroll
    for (int i2 = 0; i2 < 4; ++i2) {
        int chunk = i2 * 256 + tid;
        int r = chunk >> 3, cc = chunk & 7;
        dOff[i2] = (uint32_t)(r * PITCHB + cc * 16);
        sOff[i2] = (uint32_t)(r * 128 + cc * 16);
    }
    const char* Yb = (const char*)g_Y;

    // ---- initial loads: A(cbi), nIs, B0(cbj), nJ0 ----
    {
        const char* srcA = Yb + (size_t)cbi * 16384;
        const char* srcB = Yb + (size_t)cbj * 16384;
        #pragma unroll
        for (int i2 = 0; i2 < 4; ++i2) {
            cp_async16(sb + SMEM_A + dOff[i2], srcA + sOff[i2]);
            cp_async16(sb + SMEM_B0 + dOff[i2], srcB + sOff[i2]);
        }
        if (tid < 32) {
            cp_async16(sb + SMEM_NI + tid * 16, g_norm + cbi * BM + tid * 4);
            cp_async16(sb + SMEM_NJ0 + tid * 16, g_norm + cbj * BN + tid * 4);
        }
        cp_commit();
    }

    #pragma unroll 1
    for (int it = 0; it < cnt; ++it) {
        const int buf = it & 1;
        const uint32_t bbase = buf ? SMEM_B1 : SMEM_B0;
        const uint32_t njoff = buf ? SMEM_NJ1 : SMEM_NJ0;
        const int row0 = cbi * BM, col0 = cbj * BN;
        const bool isdiag = (cbi == cbj);

        cp_wait<0>();
        __syncthreads();

        // next tile indices; prefetch its B (+nJ) into the other buffer
        int nbi = cbi, nbj = cbj;
        bool rowchg = false;
        if (it + 1 < cnt) {
            if (cbj == MTILES - 1) { nbi = cbi + 1; nbj = nbi; rowchg = true; }
            else nbj = cbj + 1;
            const uint32_t nb = buf ? SMEM_B0 : SMEM_B1;
            const char* srcB = Yb + (size_t)nbj * 16384;
            #pragma unroll
            for (int i2 = 0; i2 < 4; ++i2)
                cp_async16(sb + nb + dOff[i2], srcB + sOff[i2]);
            if (tid < 32)
                cp_async16(sb + (buf ? SMEM_NJ0 : SMEM_NJ1) + tid * 16,
                           g_norm + nbj * BN + tid * 4);
            cp_commit();
        }

        // ---- MMA: 128x128, K=128 fp8, 4 k-steps of 32 ----
        float acc[4][4][4];
        #pragma unroll
        for (int mt = 0; mt < 4; ++mt)
            #pragma unroll
            for (int nt = 0; nt < 4; ++nt)
                #pragma unroll
                for (int e = 0; e < 4; ++e) acc[mt][nt][e] = 0.0f;

        const uint32_t aA = sb + SMEM_A + arel;
        const uint32_t aB = sb + bbase + brel;

        #pragma unroll
        for (int s = 0; s < 4; ++s) {
            const uint32_t kb = (uint32_t)(s * 32);
            uint32_t a[4][4], b[2][4];
            #pragma unroll
            for (int mt = 0; mt < 4; ++mt)
                ldsm_x4(a[mt], aA + mt * 16 * PITCHB + kb);
            #pragma unroll
            for (int p = 0; p < 2; ++p)
                ldsm_x4(b[p], aB + p * 16 * PITCHB + kb);
            #pragma unroll
            for (int mt = 0; mt < 4; ++mt) {
                mma_fp8(acc[mt][0], a[mt], &b[0][0]);
                mma_fp8(acc[mt][1], a[mt], &b[0][2]);
                mma_fp8(acc[mt][2], a[mt], &b[1][0]);
                mma_fp8(acc[mt][3], a[mt], &b[1][2]);
            }
        }

        // ---- epilogue: sim = rcp(nI + nJ + 1 - 2*dot) ----
        const float* nJs = (const float*)(smem + njoff);
        float rs[4][2], cs[4][2];
        #pragma unroll
        for (int i = 0; i < 4; ++i) rs[i][0] = rs[i][1] = 0.0f;
        #pragma unroll
        for (int i = 0; i < 4; ++i) cs[i][0] = cs[i][1] = 0.0f;

        float cI[4][2], nJ[4][2];
        #pragma unroll
        for (int mt = 0; mt < 4; ++mt) {
            cI[mt][0] = nIs[wm * 64 + mt * 16 + g] + 1.0f;
            cI[mt][1] = nIs[wm * 64 + mt * 16 + g + 8] + 1.0f;
        }
        #pragma unroll
        for (int nt = 0; nt < 4; ++nt) {
            nJ[nt][0] = nJs[wn * 32 + nt * 8 + 2 * t];
            nJ[nt][1] = nJs[wn * 32 + nt * 8 + 2 * t + 1];
        }

        if (!isdiag) {
            // HOT PATH (2016/2080 tiles)
            #pragma unroll
            for (int mt = 0; mt < 4; ++mt)
                #pragma unroll
                for (int nt = 0; nt < 4; ++nt)
                    #pragma unroll
                    for (int r = 0; r < 2; ++r)
                        #pragma unroll
                        for (int e = 0; e < 2; ++e) {
                            float dot = acc[mt][nt][r * 2 + e];
                            float sqp1 = fmaf(-2.0f, dot, cI[mt][r] + nJ[nt][e]);
                            float sim = __fdividef(1.0f, sqp1);
                            rs[mt][r] += sim;
                            cs[nt][e] += sim;
                        }
        } else {
            // DIAG PATH (64 tiles): exact self-sim override.
            #pragma unroll
            for (int mt = 0; mt < 4; ++mt)
                #pragma unroll
                for (int nt = 0; nt < 4; ++nt)
                    #pragma unroll
                    for (int r = 0; r < 2; ++r)
                        #pragma unroll
                        for (int e = 0; e < 2; ++e) {
                            float dot = acc[mt][nt][r * 2 + e];
                            float sqp1 = fmaf(-2.0f, dot, cI[mt][r] + nJ[nt][e]);
                            float sim = __fdividef(1.0f, sqp1);
                            int li = wm * 64 + mt * 16 + g + r * 8;
                            int lj = wn * 32 + nt * 8 + 2 * t + e;
                            if (li == lj) sim = 1.0f;
                            rs[mt][r] += sim;
                            cs[nt][e] += sim;
                        }
        }

        #pragma unroll
        for (int mt = 0; mt < 4; ++mt)
            #pragma unroll
            for (int r = 0; r < 2; ++r) {
                float v = rs[mt][r];
                v += __shfl_xor_sync(0xffffffffu, v, 1);
                v += __shfl_xor_sync(0xffffffffu, v, 2);
                if (t == 0)
                    atomicAdd(&g_rowsum[row0 + wm * 64 + mt * 16 + g + r * 8], v);
            }
        if (!isdiag) {
            #pragma unroll
            for (int nt = 0; nt < 4; ++nt)
                #pragma unroll
                for (int e = 0; e < 2; ++e) {
                    float v = cs[nt][e];
                    v += __shfl_xor_sync(0xffffffffu, v, 4);
                    v += __shfl_xor_sync(0xffffffffu, v, 8);
                    v += __shfl_xor_sync(0xffffffffu, v, 16);
                    if (g == 0)
                        atomicAdd(&g_rowsum[col0 + wn * 32 + nt * 8 + 2 * t + e], v);
                }
        }

        // row change: reload A + nIs
        if (rowchg) {
            __syncthreads();
            const char* srcA = Yb + (size_t)nbi * 16384;
            #pragma unroll
            for (int i2 = 0; i2 < 4; ++i2)
                cp_async16(sb + SMEM_A + dOff[i2], srcA + sOff[i2]);
            if (tid < 32)
                cp_async16(sb + SMEM_NI + tid * 16, g_norm + nbi * BM + tid * 4);
            cp_commit();
        }
        cbi = nbi; cbj = nbj;
    }
}

// ---------------------------------------------------------------------------
// Kernel 2: final scalar (+ resets g_done for graph replays).
// ---------------------------------------------------------------------------
__global__ void finalize_kernel(float* __restrict__ out) {
    __shared__ float sA[1024], s1[1024], s2[1024];
    int tid = threadIdx.x;
    if (tid == 0) g_done = 0;
    float tA = 0.0f, t1 = 0.0f, t2 = 0.0f;
    for (int i = tid; i < HALF_N; i += 1024) {
        tA += __logf(g_diag[i]);
        t2 += __logf(g_rowsum[i] - 1.0f);
        t1 += __logf(g_rowsum[i + HALF_N] - 1.0f);
    }
    sA[tid] = tA; s1[tid] = t1; s2[tid] = t2;
    __syncthreads();
    for (int s = 512; s; s >>= 1) {
        if (tid < s) {
            sA[tid] += sA[tid + s];
            s1[tid] += s1[tid + s];
            s2[tid] += s2[tid + s];
        }
        __syncthreads();
    }
    if (tid == 0) {
        float align = sA[0] * (1.0f / HALF_N);
        float lse1  = s1[0] * (1.0f / HALF_N);
        float lse2  = s2[0] * (1.0f / HALF_N);
        out[0] = -(align - 0.5f * (lse1 + lse2));
    }
}

// ---------------------------------------------------------------------------
extern "C" void kernel_launch(void* const* d_in, const int* in_sizes, int n_in,
                              void* d_out, int out_size) {
    const float* X = (const float*)d_in[0];
    float* out = (float*)d_out;

    cudaFuncSetAttribute(simsum_kernel,
                         cudaFuncAttributeMaxDynamicSharedMemorySize, SMEM_TOTAL);

    simsum_kernel<<<NCTAS, 256, SMEM_TOTAL>>>(X);
    finalize_kernel<<<1, 1024>>>(out);
}